// round 4
// baseline (speedup 1.0000x reference)
#include <cuda_runtime.h>
#include <cuda_bf16.h>

// Shower accumulator table, packed so the gather phase does ONE 16B read
// per hit.
//   x = e_track_shower (raw)     y = e_track_shower_corr
//   z = e_hit_shower   (raw)     w = e_hit_shower_corr
#define MAX_SEG 16384
#define SMEM_LIMIT (160 * 1024)
__device__ float4 g_shower[MAX_SEG];

// ---------------------------------------------------------------------------
// Kernel 1: zero the accumulator table
// ---------------------------------------------------------------------------
__global__ void zero_kernel(int nseg) {
    int i = blockIdx.x * blockDim.x + threadIdx.x;
    if (i < nseg) g_shower[i] = make_float4(0.f, 0.f, 0.f, 0.f);
}

// ---------------------------------------------------------------------------
// Kernel 2: scatter — segment-sum energies into shower bins.
// 8 hits per thread, loads front-batched, then 8 predicated global REDs.
// Noise hits (sid == -1) contribute exactly 0 in the reference -> skipped.
// recHitID==1 -> track (.x), ==0 -> hit (.z).
// ---------------------------------------------------------------------------
__global__ void __launch_bounds__(256) scatter8_kernel(
        const int* __restrict__ sid,
        const float* __restrict__ energy,
        const int* __restrict__ rid,
        int n) {
    int t = blockIdx.x * blockDim.x + threadIdx.x;
    long base = (long)t * 8;
    if (base + 8 <= n) {
        int4   s0 = __ldg((const int4*)(sid)      + 2*t);
        int4   s1 = __ldg((const int4*)(sid)      + 2*t + 1);
        float4 e0 = __ldg((const float4*)(energy) + 2*t);
        float4 e1 = __ldg((const float4*)(energy) + 2*t + 1);
        int4   r0 = __ldg((const int4*)(rid)      + 2*t);
        int4   r1 = __ldg((const int4*)(rid)      + 2*t + 1);
        int   s[8] = {s0.x, s0.y, s0.z, s0.w, s1.x, s1.y, s1.z, s1.w};
        float e[8] = {e0.x, e0.y, e0.z, e0.w, e1.x, e1.y, e1.z, e1.w};
        int   r[8] = {r0.x, r0.y, r0.z, r0.w, r1.x, r1.y, r1.z, r1.w};
#pragma unroll
        for (int k = 0; k < 8; k++) {
            if (s[k] >= 0) {
                float* p = reinterpret_cast<float*>(&g_shower[s[k] + 1]);
                atomicAdd(p + ((1 - r[k]) << 1), e[k]);
            }
        }
    } else if (base < n) {
        for (long i = base; i < n; i++) {
            int sv = sid[i];
            if (sv >= 0) {
                float* p = reinterpret_cast<float*>(&g_shower[sv + 1]);
                atomicAdd(p + ((1 - rid[i]) << 1), energy[i]);
            }
        }
    }
}

// ---------------------------------------------------------------------------
// Kernel 3: per-shower correction factors.
// corr[s] (s>=1) = pcf_ext[alpha_idx[s-1]], where pcf_ext[j] = pcf[j] if
// j < n_hits and sid[j] != -1, else 0. corr[0] = 0.
// ---------------------------------------------------------------------------
__global__ void corr_kernel(const int* __restrict__ sid,
                            const float* __restrict__ pcf,
                            const int* __restrict__ a_tracks,
                            const int* __restrict__ a_hits,
                            int n_hits, int nseg) {
    int s = blockIdx.x * blockDim.x + threadIdx.x;
    if (s >= nseg) return;
    float ct = 0.f, ch = 0.f;
    if (s > 0) {
        int jt = a_tracks[s - 1];
        if (jt >= 0 && jt < n_hits && __ldg(sid + jt) != -1) ct = __ldg(pcf + jt);
        int jh = a_hits[s - 1];
        if (jh >= 0 && jh < n_hits && __ldg(sid + jh) != -1) ch = __ldg(pcf + jh);
    }
    float4 v = g_shower[s];
    g_shower[s].y = v.x * ct;   // track corrected
    g_shower[s].w = v.z * ch;   // hit corrected
}

// ---------------------------------------------------------------------------
// Kernel 4: gather — persistent CTAs. Each CTA caches the full float4 shower
// table in SHARED memory (random LDS.128 costs only bank conflicts, not the
// 32-wavefront L1tex replay of a random global LDG.128), then streams hits:
// 1 int4 sid load -> 4 random LDS.128 -> 4 coalesced float4 stores.
// Output layout (reference tuple order):
//   [0,n)   e_track_raw   [n,2n)  e_track_corrected
//   [2n,3n) e_hit_raw     [3n,4n) e_hit_corrected
// ---------------------------------------------------------------------------
__global__ void __launch_bounds__(1024, 1) gather_smem_kernel(
        const int* __restrict__ sid,
        float* __restrict__ out,
        int n, int nseg) {
    extern __shared__ float4 tab[];
    for (int i = threadIdx.x; i < nseg; i += blockDim.x)
        tab[i] = g_shower[i];
    __syncthreads();

    long nquads = (long)n / 4;           // n divisible by 4 on this path
    long stride = (long)gridDim.x * blockDim.x;
    long s = nquads;                     // float4 stride per output stream
    float4* o = (float4*)out;

    for (long q = (long)blockIdx.x * blockDim.x + threadIdx.x; q < nquads;
         q += stride) {
        int4 a = __ldg((const int4*)(sid) + q);
        float4 v0 = tab[a.x + 1];
        float4 v1 = tab[a.y + 1];
        float4 v2 = tab[a.z + 1];
        float4 v3 = tab[a.w + 1];
        o[q]         = make_float4(v0.x, v1.x, v2.x, v3.x);  // track raw
        o[q + s]     = make_float4(v0.y, v1.y, v2.y, v3.y);  // track corrected
        o[q + 2*s]   = make_float4(v0.z, v1.z, v2.z, v3.z);  // hit raw
        o[q + 3*s]   = make_float4(v0.w, v1.w, v2.w, v3.w);  // hit corrected
    }
}

__global__ void gather_kernel_scalar(const int* __restrict__ sid,
                                     float* __restrict__ out,
                                     int n) {
    int i = blockIdx.x * blockDim.x + threadIdx.x;
    if (i >= n) return;
    float4 v = g_shower[sid[i] + 1];
    out[i]          = v.x;
    out[i + 1ll*n]  = v.y;
    out[i + 2ll*n]  = v.z;
    out[i + 3ll*n]  = v.w;
}

extern "C" void kernel_launch(void* const* d_in, const int* in_sizes, int n_in,
                              void* d_out, int out_size) {
    const int*   pred_sid = (const int*)  d_in[0];
    const float* pcf      = (const float*)d_in[1];
    const float* energy   = (const float*)d_in[2];
    const int*   rid      = (const int*)  d_in[3];
    // d_in[4] = pred_beta (unused)
    const int*   a_tracks = (const int*)  d_in[5];
    const int*   a_hits   = (const int*)  d_in[6];
    float*       out      = (float*)d_out;

    int n_hits    = in_sizes[0];
    int n_showers = in_sizes[5];
    int nseg      = n_showers + 1;
    if (nseg > MAX_SEG) nseg = MAX_SEG;

    // One-time setup (host-only, happens on the pre-capture correctness call):
    // SM count for the persistent gather grid + raised dynamic smem limit.
    // NOTE: request 160KB (<= sm_103a ~227KB/block cap). The previous round
    // asked for 256KB, which FAILED and silently disabled the smem path.
    static int sm_count = 0;
    static bool smem_ok = false;
    if (sm_count == 0) {
        cudaDeviceProp prop;
        cudaGetDeviceProperties(&prop, 0);
        sm_count = prop.multiProcessorCount;
        if (sm_count <= 0) sm_count = 148;
        smem_ok = (cudaFuncSetAttribute(
                       gather_smem_kernel,
                       cudaFuncAttributeMaxDynamicSharedMemorySize,
                       SMEM_LIMIT) == cudaSuccess);
    }

    const int TPB = 256;

    zero_kernel<<<(nseg + TPB - 1) / TPB, TPB>>>(nseg);

    int n8 = (n_hits + 7) / 8;
    scatter8_kernel<<<(n8 + TPB - 1) / TPB, TPB>>>(pred_sid, energy, rid, n_hits);

    corr_kernel<<<(nseg + TPB - 1) / TPB, TPB>>>(pred_sid, pcf, a_tracks, a_hits,
                                                 n_hits, nseg);

    size_t smem_bytes = (size_t)nseg * sizeof(float4);
    if ((n_hits & 3) == 0 && smem_ok && smem_bytes <= SMEM_LIMIT) {
        gather_smem_kernel<<<sm_count, 1024, smem_bytes>>>(pred_sid, out,
                                                           n_hits, nseg);
    } else {
        gather_kernel_scalar<<<(n_hits + TPB - 1) / TPB, TPB>>>(pred_sid, out,
                                                                n_hits);
    }
}

// round 5
// speedup vs baseline: 1.1230x; 1.1230x over previous
#include <cuda_runtime.h>
#include <cuda_bf16.h>

#define MAX_SEG 16384
#define PAD 8   // one float counter per 32B sector (8 floats)

// Padded scatter accumulators: one counter per 32B sector, track and hit in
// separate arrays (no two hot atomics share an L2 sector).
__device__ float g_track[MAX_SEG * PAD];
__device__ float g_hit[MAX_SEG * PAD];

// Packed table for the gather phase: ONE 16B read per hit.
//   x = e_track_raw  y = e_track_corr  z = e_hit_raw  w = e_hit_corr
__device__ float4 g_shower[MAX_SEG];

// ---------------------------------------------------------------------------
// Kernel 1: zero the padded accumulators (only the used slots)
// ---------------------------------------------------------------------------
__global__ void zero_kernel(int nseg) {
    int i = blockIdx.x * blockDim.x + threadIdx.x;
    if (i < nseg) {
        g_track[i * PAD] = 0.f;
        g_hit[i * PAD]   = 0.f;
    }
}

// ---------------------------------------------------------------------------
// Kernel 2: scatter — segment-sum energies into padded per-shower counters.
// 8 hits per thread, loads front-batched, then 8 predicated global REDs.
// Noise hits (sid == -1) contribute exactly 0 in the reference -> skipped.
// recHitID==1 -> track, ==0 -> hit.
// ---------------------------------------------------------------------------
__global__ void __launch_bounds__(256) scatter8_kernel(
        const int* __restrict__ sid,
        const float* __restrict__ energy,
        const int* __restrict__ rid,
        int n) {
    int t = blockIdx.x * blockDim.x + threadIdx.x;
    long base = (long)t * 8;
    if (base + 8 <= n) {
        int4   s0 = __ldg((const int4*)(sid)      + 2*t);
        int4   s1 = __ldg((const int4*)(sid)      + 2*t + 1);
        float4 e0 = __ldg((const float4*)(energy) + 2*t);
        float4 e1 = __ldg((const float4*)(energy) + 2*t + 1);
        int4   r0 = __ldg((const int4*)(rid)      + 2*t);
        int4   r1 = __ldg((const int4*)(rid)      + 2*t + 1);
        int   s[8] = {s0.x, s0.y, s0.z, s0.w, s1.x, s1.y, s1.z, s1.w};
        float e[8] = {e0.x, e0.y, e0.z, e0.w, e1.x, e1.y, e1.z, e1.w};
        int   r[8] = {r0.x, r0.y, r0.z, r0.w, r1.x, r1.y, r1.z, r1.w};
#pragma unroll
        for (int k = 0; k < 8; k++) {
            if (s[k] >= 0) {
                float* p = (r[k] == 1) ? &g_track[(s[k] + 1) * PAD]
                                       : &g_hit[(s[k] + 1) * PAD];
                atomicAdd(p, e[k]);
            }
        }
    } else if (base < n) {
        for (long i = base; i < n; i++) {
            int sv = sid[i];
            if (sv >= 0) {
                float* p = (rid[i] == 1) ? &g_track[(sv + 1) * PAD]
                                         : &g_hit[(sv + 1) * PAD];
                atomicAdd(p, energy[i]);
            }
        }
    }
}

// ---------------------------------------------------------------------------
// Kernel 3: per-shower correction + repack padded sums into the float4 table.
// corr[s] (s>=1) = pcf_ext[alpha_idx[s-1]], where pcf_ext[j] = pcf[j] if
// j < n_hits and sid[j] != -1, else 0. corr[0] = 0.
// ---------------------------------------------------------------------------
__global__ void corr_kernel(const int* __restrict__ sid,
                            const float* __restrict__ pcf,
                            const int* __restrict__ a_tracks,
                            const int* __restrict__ a_hits,
                            int n_hits, int nseg) {
    int s = blockIdx.x * blockDim.x + threadIdx.x;
    if (s >= nseg) return;
    float ct = 0.f, ch = 0.f;
    if (s > 0) {
        int jt = a_tracks[s - 1];
        if (jt >= 0 && jt < n_hits && __ldg(sid + jt) != -1) ct = __ldg(pcf + jt);
        int jh = a_hits[s - 1];
        if (jh >= 0 && jh < n_hits && __ldg(sid + jh) != -1) ch = __ldg(pcf + jh);
    }
    float et = g_track[s * PAD];
    float eh = g_hit[s * PAD];
    g_shower[s] = make_float4(et, et * ct, eh, eh * ch);
}

// ---------------------------------------------------------------------------
// Kernel 4: gather — scalar form (measured at its L1tex-wavefront floor):
// one random 16B LDG per hit + 4 coalesced 4B stores.
// Output layout (reference tuple order):
//   [0,n)   e_track_raw   [n,2n)  e_track_corrected
//   [2n,3n) e_hit_raw     [3n,4n) e_hit_corrected
// ---------------------------------------------------------------------------
__global__ void __launch_bounds__(256) gather_kernel_scalar(
        const int* __restrict__ sid,
        float* __restrict__ out,
        int n) {
    int i = blockIdx.x * blockDim.x + threadIdx.x;
    if (i >= n) return;
    float4 v = g_shower[__ldg(sid + i) + 1];
    out[i]          = v.x;
    out[i + 1ll*n]  = v.y;
    out[i + 2ll*n]  = v.z;
    out[i + 3ll*n]  = v.w;
}

extern "C" void kernel_launch(void* const* d_in, const int* in_sizes, int n_in,
                              void* d_out, int out_size) {
    const int*   pred_sid = (const int*)  d_in[0];
    const float* pcf      = (const float*)d_in[1];
    const float* energy   = (const float*)d_in[2];
    const int*   rid      = (const int*)  d_in[3];
    // d_in[4] = pred_beta (unused)
    const int*   a_tracks = (const int*)  d_in[5];
    const int*   a_hits   = (const int*)  d_in[6];
    float*       out      = (float*)d_out;

    int n_hits    = in_sizes[0];
    int n_showers = in_sizes[5];
    int nseg      = n_showers + 1;
    if (nseg > MAX_SEG) nseg = MAX_SEG;

    const int TPB = 256;

    zero_kernel<<<(nseg + TPB - 1) / TPB, TPB>>>(nseg);

    int n8 = (n_hits + 7) / 8;
    scatter8_kernel<<<(n8 + TPB - 1) / TPB, TPB>>>(pred_sid, energy, rid, n_hits);

    corr_kernel<<<(nseg + TPB - 1) / TPB, TPB>>>(pred_sid, pcf, a_tracks, a_hits,
                                                 n_hits, nseg);

    gather_kernel_scalar<<<(n_hits + TPB - 1) / TPB, TPB>>>(pred_sid, out,
                                                            n_hits);
}

// round 6
// speedup vs baseline: 1.1585x; 1.0316x over previous
#include <cuda_runtime.h>
#include <cuda_bf16.h>

#define MAX_SEG 16384
#define PAD 8   // one float counter per 32B L2 sector

// Padded scatter accumulators: one counter per 32B sector, track and hit in
// separate arrays (no two hot atomics share an L2 sector).
// NOTE: zero-initialized at module load; corr_kernel re-zeroes them after
// reading, so every kernel_launch call starts from a clean state without a
// dedicated zeroing kernel.
__device__ float g_track[MAX_SEG * PAD];
__device__ float g_hit[MAX_SEG * PAD];

// Packed table for the gather phase: ONE 16B read per hit.
//   x = e_track_raw  y = e_track_corr  z = e_hit_raw  w = e_hit_corr
__device__ float4 g_shower[MAX_SEG];

// ---------------------------------------------------------------------------
// Kernel 1: scatter — segment-sum energies into padded per-shower counters.
// 8 hits per thread, loads front-batched, then 8 predicated global REDs.
// Noise hits (sid == -1) contribute exactly 0 in the reference -> skipped.
// recHitID==1 -> track, ==0 -> hit.
// ---------------------------------------------------------------------------
__global__ void __launch_bounds__(256) scatter8_kernel(
        const int* __restrict__ sid,
        const float* __restrict__ energy,
        const int* __restrict__ rid,
        int n) {
    int t = blockIdx.x * blockDim.x + threadIdx.x;
    long base = (long)t * 8;
    if (base + 8 <= n) {
        int4   s0 = __ldg((const int4*)(sid)      + 2*t);
        int4   s1 = __ldg((const int4*)(sid)      + 2*t + 1);
        float4 e0 = __ldg((const float4*)(energy) + 2*t);
        float4 e1 = __ldg((const float4*)(energy) + 2*t + 1);
        int4   r0 = __ldg((const int4*)(rid)      + 2*t);
        int4   r1 = __ldg((const int4*)(rid)      + 2*t + 1);
        int   s[8] = {s0.x, s0.y, s0.z, s0.w, s1.x, s1.y, s1.z, s1.w};
        float e[8] = {e0.x, e0.y, e0.z, e0.w, e1.x, e1.y, e1.z, e1.w};
        int   r[8] = {r0.x, r0.y, r0.z, r0.w, r1.x, r1.y, r1.z, r1.w};
#pragma unroll
        for (int k = 0; k < 8; k++) {
            if (s[k] >= 0) {
                float* p = (r[k] == 1) ? &g_track[(s[k] + 1) * PAD]
                                       : &g_hit[(s[k] + 1) * PAD];
                atomicAdd(p, e[k]);
            }
        }
    } else if (base < n) {
        for (long i = base; i < n; i++) {
            int sv = sid[i];
            if (sv >= 0) {
                float* p = (rid[i] == 1) ? &g_track[(sv + 1) * PAD]
                                         : &g_hit[(sv + 1) * PAD];
                atomicAdd(p, energy[i]);
            }
        }
    }
}

// ---------------------------------------------------------------------------
// Kernel 2: per-shower correction + repack padded sums into the float4 table,
// then re-zero the accumulators (leaves them clean for the next call).
// corr[s] (s>=1) = pcf_ext[alpha_idx[s-1]], where pcf_ext[j] = pcf[j] if
// j < n_hits and sid[j] != -1, else 0. corr[0] = 0.
// ---------------------------------------------------------------------------
__global__ void corr_kernel(const int* __restrict__ sid,
                            const float* __restrict__ pcf,
                            const int* __restrict__ a_tracks,
                            const int* __restrict__ a_hits,
                            int n_hits, int nseg) {
    int s = blockIdx.x * blockDim.x + threadIdx.x;
    if (s >= nseg) return;
    float ct = 0.f, ch = 0.f;
    if (s > 0) {
        int jt = a_tracks[s - 1];
        if (jt >= 0 && jt < n_hits && __ldg(sid + jt) != -1) ct = __ldg(pcf + jt);
        int jh = a_hits[s - 1];
        if (jh >= 0 && jh < n_hits && __ldg(sid + jh) != -1) ch = __ldg(pcf + jh);
    }
    float et = g_track[s * PAD];
    float eh = g_hit[s * PAD];
    g_shower[s] = make_float4(et, et * ct, eh, eh * ch);
    g_track[s * PAD] = 0.f;   // self-clean for the next launch
    g_hit[s * PAD]   = 0.f;
}

// ---------------------------------------------------------------------------
// Kernel 3: gather — 4 hits/thread (best measured variant, R1: 16.9us):
// 1 int4 sid load -> 4 independent random 16B table reads -> 4 coalesced
// float4 stores. Output layout (reference tuple order):
//   [0,n)   e_track_raw   [n,2n)  e_track_corrected
//   [2n,3n) e_hit_raw     [3n,4n) e_hit_corrected
// ---------------------------------------------------------------------------
__global__ void __launch_bounds__(256) gather_kernel_vec(
        const int* __restrict__ sid,
        float* __restrict__ out,
        int n) {
    int t = blockIdx.x * blockDim.x + threadIdx.x;
    if ((long)t * 4 >= n) return;
    int4 s4 = __ldg((const int4*)(sid) + t);
    float4 v0 = g_shower[s4.x + 1];
    float4 v1 = g_shower[s4.y + 1];
    float4 v2 = g_shower[s4.z + 1];
    float4 v3 = g_shower[s4.w + 1];
    float4* o0 = (float4*)(out)          + t;
    float4* o1 = (float4*)(out + n)      + t;
    float4* o2 = (float4*)(out + 2ll*n)  + t;
    float4* o3 = (float4*)(out + 3ll*n)  + t;
    *o0 = make_float4(v0.x, v1.x, v2.x, v3.x);  // track raw
    *o1 = make_float4(v0.y, v1.y, v2.y, v3.y);  // track corrected
    *o2 = make_float4(v0.z, v1.z, v2.z, v3.z);  // hit raw
    *o3 = make_float4(v0.w, v1.w, v2.w, v3.w);  // hit corrected
}

__global__ void gather_kernel_scalar(const int* __restrict__ sid,
                                     float* __restrict__ out,
                                     int n) {
    int i = blockIdx.x * blockDim.x + threadIdx.x;
    if (i >= n) return;
    float4 v = g_shower[__ldg(sid + i) + 1];
    out[i]          = v.x;
    out[i + 1ll*n]  = v.y;
    out[i + 2ll*n]  = v.z;
    out[i + 3ll*n]  = v.w;
}

extern "C" void kernel_launch(void* const* d_in, const int* in_sizes, int n_in,
                              void* d_out, int out_size) {
    const int*   pred_sid = (const int*)  d_in[0];
    const float* pcf      = (const float*)d_in[1];
    const float* energy   = (const float*)d_in[2];
    const int*   rid      = (const int*)  d_in[3];
    // d_in[4] = pred_beta (unused)
    const int*   a_tracks = (const int*)  d_in[5];
    const int*   a_hits   = (const int*)  d_in[6];
    float*       out      = (float*)d_out;

    int n_hits    = in_sizes[0];
    int n_showers = in_sizes[5];
    int nseg      = n_showers + 1;
    if (nseg > MAX_SEG) nseg = MAX_SEG;

    const int TPB = 256;

    int n8 = (n_hits + 7) / 8;
    scatter8_kernel<<<(n8 + TPB - 1) / TPB, TPB>>>(pred_sid, energy, rid, n_hits);

    corr_kernel<<<(nseg + TPB - 1) / TPB, TPB>>>(pred_sid, pcf, a_tracks, a_hits,
                                                 n_hits, nseg);

    if ((n_hits & 3) == 0) {
        int n4 = n_hits / 4;
        gather_kernel_vec<<<(n4 + TPB - 1) / TPB, TPB>>>(pred_sid, out, n_hits);
    } else {
        gather_kernel_scalar<<<(n_hits + TPB - 1) / TPB, TPB>>>(pred_sid, out,
                                                                n_hits);
    }
}